// round 1
// baseline (speedup 1.0000x reference)
#include <cuda_runtime.h>
#include <math.h>

#define D1 512
#define D2 1024
#define NS 16
#define MMAX 16384
#define LMASK 4095

// ---------------- scratch (static device globals; no allocation) ----------------
__device__ float g_xn[(size_t)MMAX * D1];
__device__ float g_t0[(size_t)MMAX * D2];
__device__ float g_t1[(size_t)MMAX * D2];
__device__ float g_t2[(size_t)MMAX * D2];
__device__ float g_cb[MMAX];

// ---------------- f32x2 packed math helpers ----------------
__device__ __forceinline__ unsigned long long fma2(unsigned long long a,
                                                   unsigned long long b,
                                                   unsigned long long c) {
    unsigned long long d;
    asm("fma.rn.f32x2 %0, %1, %2, %3;" : "=l"(d) : "l"(a), "l"(b), "l"(c));
    return d;
}
__device__ __forceinline__ unsigned long long dup2(float v) {
    unsigned long long d;
    unsigned int r = __float_as_uint(v);
    asm("mov.b64 %0, {%1, %1};" : "=l"(d) : "r"(r));
    return d;
}
__device__ __forceinline__ float lo2(unsigned long long v) {
    return __uint_as_float((unsigned int)v);
}
__device__ __forceinline__ float hi2(unsigned long long v) {
    return __uint_as_float((unsigned int)(v >> 32));
}

__device__ __forceinline__ float softplus_f(float x) {
    return (x > 20.0f) ? x : log1pf(expf(x));
}
__device__ __forceinline__ float swish_f(float x) {
    return x / (1.0f + expf(-x));
}

// ---------------- rmsnorm ----------------
__global__ void rmsnorm_kernel(const float* __restrict__ x,
                               const float* __restrict__ w,
                               float* __restrict__ y) {
    int row = blockIdx.x;
    int t = threadIdx.x;  // 128 threads, each 1 float4 (D1=512)
    const float4* xr = (const float4*)(x + (size_t)row * D1);
    float4 xv = xr[t];
    float ss = xv.x * xv.x + xv.y * xv.y + xv.z * xv.z + xv.w * xv.w;
#pragma unroll
    for (int off = 16; off; off >>= 1) ss += __shfl_xor_sync(0xffffffffu, ss, off);
    __shared__ float sred[4];
    if ((t & 31) == 0) sred[t >> 5] = ss;
    __syncthreads();
    float tot = sred[0] + sred[1] + sred[2] + sred[3];
    float s = rsqrtf(tot * (1.0f / (float)D1) + 1e-5f);
    float4 wv = ((const float4*)w)[t];
    float4 o;
    o.x = xv.x * s * wv.x;
    o.y = xv.y * s * wv.y;
    o.z = xv.z * s * wv.z;
    o.w = xv.w * s * wv.w;
    ((float4*)(y + (size_t)row * D1))[t] = o;
}

// ---------------- conv-as-3-shifted-GEMMs ----------------
// Y[m,n] = act( sum_{koff,c} X[m+koff-1, c] * W[koff,c,n] + bias[n] )
// ACT: 0 = identity, 1 = swish, 2 = s6 epilogue (xc * softplus(v) * cb[m] * xr)
template <int ACT>
__global__ __launch_bounds__(256) void conv_gemm(
    const float* __restrict__ X, const float* __restrict__ W,
    const float* __restrict__ bias, float* __restrict__ Y,
    int Cin, int Cout, int M,
    const float* __restrict__ xc, const float* __restrict__ xr,
    const float* __restrict__ cbv) {
    const int BM = 128, BN = 64, BK = 16;
    __shared__ float As[BK][BM];
    __shared__ float Bs[BK][BN];

    int tid = threadIdx.x;
    int bm = blockIdx.y * BM;
    int bn = blockIdx.x * BN;
    int tx = tid & 15;   // 0..15 -> 4 cols each
    int ty = tid >> 4;   // 0..15 -> 8 rows each

    unsigned long long acc[4][4];
#pragma unroll
    for (int p = 0; p < 4; p++)
#pragma unroll
        for (int j = 0; j < 4; j++) acc[p][j] = 0ull;

    // A-tile load mapping: thread loads 8 consecutive k for one m
    int am = tid >> 1;            // 0..127
    int akh = (tid & 1) * 8;      // 0 or 8
    // B-tile load mapping: one float4 along n
    int bk = tid >> 4;            // 0..15
    int bn4 = (tid & 15) * 4;     // 0..60

    for (int koff = 0; koff < 3; ++koff) {
        int pos = (bm + am) & LMASK;
        bool valid = !((koff == 0 && pos == 0) || (koff == 2 && pos == LMASK));
        const float* Arow = X + (size_t)(bm + am + koff - 1) * Cin;
        const float* Wk = W + (size_t)koff * Cin * Cout;

        for (int kc = 0; kc < Cin; kc += BK) {
            float4 a0 = make_float4(0.f, 0.f, 0.f, 0.f);
            float4 a1 = a0;
            if (valid) {
                const float4* Ap = (const float4*)(Arow + kc + akh);
                a0 = Ap[0];
                a1 = Ap[1];
            }
            As[akh + 0][am] = a0.x; As[akh + 1][am] = a0.y;
            As[akh + 2][am] = a0.z; As[akh + 3][am] = a0.w;
            As[akh + 4][am] = a1.x; As[akh + 5][am] = a1.y;
            As[akh + 6][am] = a1.z; As[akh + 7][am] = a1.w;

            float4 bv4 = *(const float4*)(Wk + (size_t)(kc + bk) * Cout + bn + bn4);
            *(float4*)&Bs[bk][bn4] = bv4;
            __syncthreads();

#pragma unroll
            for (int k = 0; k < BK; k++) {
                const unsigned long long* Ap2 =
                    (const unsigned long long*)&As[k][ty * 8];
                unsigned long long a20 = Ap2[0], a21 = Ap2[1], a22 = Ap2[2], a23 = Ap2[3];
                float4 bb = *(const float4*)&Bs[k][tx * 4];
                unsigned long long b0 = dup2(bb.x), b1 = dup2(bb.y),
                                   b2 = dup2(bb.z), b3 = dup2(bb.w);
                acc[0][0] = fma2(a20, b0, acc[0][0]);
                acc[0][1] = fma2(a20, b1, acc[0][1]);
                acc[0][2] = fma2(a20, b2, acc[0][2]);
                acc[0][3] = fma2(a20, b3, acc[0][3]);
                acc[1][0] = fma2(a21, b0, acc[1][0]);
                acc[1][1] = fma2(a21, b1, acc[1][1]);
                acc[1][2] = fma2(a21, b2, acc[1][2]);
                acc[1][3] = fma2(a21, b3, acc[1][3]);
                acc[2][0] = fma2(a22, b0, acc[2][0]);
                acc[2][1] = fma2(a22, b1, acc[2][1]);
                acc[2][2] = fma2(a22, b2, acc[2][2]);
                acc[2][3] = fma2(a22, b3, acc[2][3]);
                acc[3][0] = fma2(a23, b0, acc[3][0]);
                acc[3][1] = fma2(a23, b1, acc[3][1]);
                acc[3][2] = fma2(a23, b2, acc[3][2]);
                acc[3][3] = fma2(a23, b3, acc[3][3]);
            }
            __syncthreads();
        }
    }

    // epilogue
    int c0 = bn + tx * 4;
    float4 bvec = *(const float4*)&bias[c0];
#pragma unroll
    for (int p = 0; p < 4; p++) {
#pragma unroll
        for (int h = 0; h < 2; h++) {
            int row = bm + ty * 8 + p * 2 + h;
            float v0, v1, v2, v3;
            if (h == 0) {
                v0 = lo2(acc[p][0]); v1 = lo2(acc[p][1]);
                v2 = lo2(acc[p][2]); v3 = lo2(acc[p][3]);
            } else {
                v0 = hi2(acc[p][0]); v1 = hi2(acc[p][1]);
                v2 = hi2(acc[p][2]); v3 = hi2(acc[p][3]);
            }
            v0 += bvec.x; v1 += bvec.y; v2 += bvec.z; v3 += bvec.w;
            float4 o;
            if (ACT == 0) {
                o.x = v0; o.y = v1; o.z = v2; o.w = v3;
            } else if (ACT == 1) {
                o.x = swish_f(v0); o.y = swish_f(v1);
                o.z = swish_f(v2); o.w = swish_f(v3);
            } else {
                float c = cbv[row];
                const float* xcr = xc + (size_t)row * Cout + c0;
                const float* xrr = xr + (size_t)row * Cout + c0;
                float4 xcv = *(const float4*)xcr;
                float4 xrv = *(const float4*)xrr;
                o.x = xcv.x * softplus_f(v0) * c * xrv.x;
                o.y = xcv.y * softplus_f(v1) * c * xrv.y;
                o.z = xcv.z * softplus_f(v2) * c * xrv.z;
                o.w = xcv.w * softplus_f(v3) * c * xrv.w;
            }
            *(float4*)&Y[(size_t)row * Cout + c0] = o;
        }
    }
}

// ---------------- fused fc2/fc3 conv + cb scalar ----------------
// cb[m] = sum_n (Bm[m,n]+b2[n]) * (Cm[m,n]+b3[n]),   Bm/Cm = K=3 convs to 16 chans
__global__ void bc_kernel(const float* __restrict__ X,
                          const float* __restrict__ w2, const float* __restrict__ b2,
                          const float* __restrict__ w3, const float* __restrict__ b3,
                          float* __restrict__ cbout, int M) {
    int warp = (int)((blockIdx.x * blockDim.x + threadIdx.x) >> 5);
    int lane = threadIdx.x & 31;
    if (warp >= M) return;
    float accB[NS], accC[NS];
#pragma unroll
    for (int n = 0; n < NS; n++) { accB[n] = 0.f; accC[n] = 0.f; }
    int pos = warp & LMASK;
    for (int koff = 0; koff < 3; koff++) {
        if ((koff == 0 && pos == 0) || (koff == 2 && pos == LMASK)) continue;
        const float* xrow = X + (size_t)(warp + koff - 1) * D2;
        const float* w2k = w2 + (size_t)koff * D2 * NS;
        const float* w3k = w3 + (size_t)koff * D2 * NS;
        for (int c = lane; c < D2; c += 32) {
            float xv = xrow[c];
            const float4* w2p = (const float4*)(w2k + (size_t)c * NS);
            const float4* w3p = (const float4*)(w3k + (size_t)c * NS);
#pragma unroll
            for (int q = 0; q < 4; q++) {
                float4 wv = w2p[q];
                accB[q * 4 + 0] += xv * wv.x;
                accB[q * 4 + 1] += xv * wv.y;
                accB[q * 4 + 2] += xv * wv.z;
                accB[q * 4 + 3] += xv * wv.w;
                float4 wv3 = w3p[q];
                accC[q * 4 + 0] += xv * wv3.x;
                accC[q * 4 + 1] += xv * wv3.y;
                accC[q * 4 + 2] += xv * wv3.z;
                accC[q * 4 + 3] += xv * wv3.w;
            }
        }
    }
#pragma unroll
    for (int n = 0; n < NS; n++) {
#pragma unroll
        for (int off = 16; off; off >>= 1) {
            accB[n] += __shfl_xor_sync(0xffffffffu, accB[n], off);
            accC[n] += __shfl_xor_sync(0xffffffffu, accC[n], off);
        }
    }
    if (lane == 0) {
        float s = 0.f;
#pragma unroll
        for (int n = 0; n < NS; n++) s += (accB[n] + b2[n]) * (accC[n] + b3[n]);
        cbout[warp] = s;
    }
}

// ---------------- launch ----------------
extern "C" void kernel_launch(void* const* d_in, const int* in_sizes, int n_in,
                              void* d_out, int out_size) {
    const float* x      = (const float*)d_in[0];
    const float* norm_w = (const float*)d_in[1];
    const float* inp_w  = (const float*)d_in[2];
    const float* inp_b  = (const float*)d_in[3];
    const float* conv_w = (const float*)d_in[4];
    const float* conv_b = (const float*)d_in[5];
    const float* cl_w   = (const float*)d_in[6];
    const float* cl_b   = (const float*)d_in[7];
    const float* fc1_w  = (const float*)d_in[8];
    const float* fc1_b  = (const float*)d_in[9];
    const float* fc2_w  = (const float*)d_in[10];
    const float* fc2_b  = (const float*)d_in[11];
    const float* fc3_w  = (const float*)d_in[12];
    const float* fc3_b  = (const float*)d_in[13];
    // d_in[14] = A (mathematically dead: dA multiplies a zero state)
    const float* res_w  = (const float*)d_in[15];
    const float* res_b  = (const float*)d_in[16];
    const float* out_w  = (const float*)d_in[17];
    const float* out_b  = (const float*)d_in[18];

    int M = in_sizes[0] / D1;  // 16384

    float *xn, *t0, *t1, *t2, *cb;
    cudaGetSymbolAddress((void**)&xn, g_xn);
    cudaGetSymbolAddress((void**)&t0, g_t0);
    cudaGetSymbolAddress((void**)&t1, g_t1);
    cudaGetSymbolAddress((void**)&t2, g_t2);
    cudaGetSymbolAddress((void**)&cb, g_cb);

    // 1) xn = rmsnorm(x)
    rmsnorm_kernel<<<M, 128>>>(x, norm_w, xn);

    dim3 blk(256);
    dim3 g_big(D2 / 64, M / 128);
    dim3 g_out(D1 / 64, M / 128);

    // 2) t0 = conv(xn, inp)                [512 -> 1024]
    conv_gemm<0><<<g_big, blk>>>(xn, inp_w, inp_b, t0, D1, D2, M, nullptr, nullptr, nullptr);
    // 3) t1 = swish(conv(t0, conv))        [1024 -> 1024]
    conv_gemm<1><<<g_big, blk>>>(t0, conv_w, conv_b, t1, D2, D2, M, nullptr, nullptr, nullptr);
    // 4) t2 = conv(t1, cl)  = x_conv_out   [1024 -> 1024]
    conv_gemm<0><<<g_big, blk>>>(t1, cl_w, cl_b, t2, D2, D2, M, nullptr, nullptr, nullptr);
    // 5) cb[m] from fc2/fc3 convs of t2
    bc_kernel<<<(M * 32 + 255) / 256, 256>>>(t2, fc2_w, fc2_b, fc3_w, fc3_b, cb, M);
    // 6) t1 = x_res = swish(conv(xn, res)) [512 -> 1024] (t1 is free now)
    conv_gemm<1><<<g_big, blk>>>(xn, res_w, res_b, t1, D1, D2, M, nullptr, nullptr, nullptr);
    // 7) t0 = x_ssm * x_res = t2 * softplus(conv(t2,fc1)) * cb * t1
    conv_gemm<2><<<g_big, blk>>>(t2, fc1_w, fc1_b, t0, D2, D2, M, t2, t1, cb);
    // 8) out = conv(t0, out)               [1024 -> 512]
    conv_gemm<0><<<g_out, blk>>>(t0, out_w, out_b, (float*)d_out, D2, D1, M, nullptr, nullptr, nullptr);
}

// round 3
// speedup vs baseline: 2.1283x; 2.1283x over previous
#include <cuda_runtime.h>
#include <cuda_bf16.h>
#include <math.h>
#include <cstdint>

#define D1 512
#define D2 1024
#define NS 16
#define MTOT 16384
#define LMASK 4095

// ---------------- scratch (static device globals; no allocation) ----------------
__device__ __nv_bfloat16 g_xnh[(size_t)MTOT * D1];
__device__ __nv_bfloat16 g_xnl[(size_t)MTOT * D1];
__device__ __nv_bfloat16 g_t0h[(size_t)MTOT * D2];
__device__ __nv_bfloat16 g_t0l[(size_t)MTOT * D2];
__device__ __nv_bfloat16 g_t1h[(size_t)MTOT * D2];
__device__ __nv_bfloat16 g_t1l[(size_t)MTOT * D2];
__device__ __nv_bfloat16 g_t2h[(size_t)MTOT * D2];
__device__ __nv_bfloat16 g_t2l[(size_t)MTOT * D2];
__device__ float g_cb[MTOT];
// transposed+split weights: [koff][Cout][Cin]
__device__ __nv_bfloat16 g_wInpH[3 * D1 * D2], g_wInpL[3 * D1 * D2];
__device__ __nv_bfloat16 g_wCnvH[3 * D2 * D2], g_wCnvL[3 * D2 * D2];
__device__ __nv_bfloat16 g_wClH[3 * D2 * D2],  g_wClL[3 * D2 * D2];
__device__ __nv_bfloat16 g_wF1H[3 * D2 * D2],  g_wF1L[3 * D2 * D2];
__device__ __nv_bfloat16 g_wResH[3 * D1 * D2], g_wResL[3 * D1 * D2];
__device__ __nv_bfloat16 g_wOutH[3 * D2 * D1], g_wOutL[3 * D2 * D1];

// ---------------- small math ----------------
__device__ __forceinline__ float softplus_f(float x) {
    return (x > 20.0f) ? x : log1pf(expf(x));
}
__device__ __forceinline__ float swish_f(float x) {
    return x / (1.0f + expf(-x));
}

// ---------------- ptx helpers ----------------
__device__ __forceinline__ uint32_t s2u(const void* p) {
    uint32_t a;
    asm("{ .reg .u64 t; cvta.to.shared.u64 t, %1; cvt.u32.u64 %0, t; }"
        : "=r"(a) : "l"(p));
    return a;
}
__device__ __forceinline__ void cp16(uint32_t saddr, const void* gaddr, uint32_t sz) {
    asm volatile("cp.async.ca.shared.global [%0], [%1], 16, %2;"
                 :: "r"(saddr), "l"(gaddr), "r"(sz) : "memory");
}
__device__ __forceinline__ void cp_commit() {
    asm volatile("cp.async.commit_group;" ::: "memory");
}
template <int N>
__device__ __forceinline__ void cp_wait() {
    asm volatile("cp.async.wait_group %0;" :: "n"(N) : "memory");
}
__device__ __forceinline__ void ldsm4(uint32_t* r, uint32_t addr) {
    asm volatile("ldmatrix.sync.aligned.m8n8.x4.shared.b16 {%0,%1,%2,%3}, [%4];"
                 : "=r"(r[0]), "=r"(r[1]), "=r"(r[2]), "=r"(r[3]) : "r"(addr));
}
__device__ __forceinline__ void mma16816(float* d, const uint32_t* a,
                                         const uint32_t* b) {
    asm volatile(
        "mma.sync.aligned.m16n8k16.row.col.f32.bf16.bf16.f32 "
        "{%0,%1,%2,%3}, {%4,%5,%6,%7}, {%8,%9}, {%0,%1,%2,%3};"
        : "+f"(d[0]), "+f"(d[1]), "+f"(d[2]), "+f"(d[3])
        : "r"(a[0]), "r"(a[1]), "r"(a[2]), "r"(a[3]), "r"(b[0]), "r"(b[1]));
}

// ---------------- rmsnorm -> hi/lo bf16 ----------------
__global__ void rmsnorm_split(const float* __restrict__ x,
                              const float* __restrict__ w,
                              __nv_bfloat16* __restrict__ yh,
                              __nv_bfloat16* __restrict__ yl) {
    int row = blockIdx.x;
    int t = threadIdx.x;  // 128 threads * float4
    const float4* xr = (const float4*)(x + (size_t)row * D1);
    float4 xv = xr[t];
    float ss = xv.x * xv.x + xv.y * xv.y + xv.z * xv.z + xv.w * xv.w;
#pragma unroll
    for (int off = 16; off; off >>= 1) ss += __shfl_xor_sync(0xffffffffu, ss, off);
    __shared__ float sred[4];
    if ((t & 31) == 0) sred[t >> 5] = ss;
    __syncthreads();
    float tot = sred[0] + sred[1] + sred[2] + sred[3];
    float s = rsqrtf(tot * (1.0f / (float)D1) + 1e-5f);
    float4 wv = ((const float4*)w)[t];
    float o[4];
    o[0] = xv.x * s * wv.x; o[1] = xv.y * s * wv.y;
    o[2] = xv.z * s * wv.z; o[3] = xv.w * s * wv.w;
    size_t base = (size_t)row * D1 + t * 4;
#pragma unroll
    for (int j = 0; j < 4; j += 2) {
        __nv_bfloat16 h0 = __float2bfloat16(o[j]);
        __nv_bfloat16 h1 = __float2bfloat16(o[j + 1]);
        __nv_bfloat162 hp; hp.x = h0; hp.y = h1;
        *(__nv_bfloat162*)(yh + base + j) = hp;
        __nv_bfloat162 lp;
        lp.x = __float2bfloat16(o[j] - __bfloat162float(h0));
        lp.y = __float2bfloat16(o[j + 1] - __bfloat162float(h1));
        *(__nv_bfloat162*)(yl + base + j) = lp;
    }
}

// ---------------- weight transpose + split: W[k][Cin][Cout] -> T[k][Cout][Cin] ----------------
__global__ void wsplit_T(const float* __restrict__ W,
                         __nv_bfloat16* __restrict__ Th,
                         __nv_bfloat16* __restrict__ Tl,
                         int Cin, int Cout) {
    __shared__ float tile[32][33];
    int koff = blockIdx.z;
    int n0 = blockIdx.x * 32;
    int c0 = blockIdx.y * 32;
    int tx = threadIdx.x, ty = threadIdx.y;  // 32 x 8
    const float* Wk = W + (size_t)koff * Cin * Cout;
#pragma unroll
    for (int r = 0; r < 32; r += 8)
        tile[ty + r][tx] = Wk[(size_t)(c0 + ty + r) * Cout + n0 + tx];
    __syncthreads();
    __nv_bfloat16* Thk = Th + (size_t)koff * Cin * Cout;
    __nv_bfloat16* Tlk = Tl + (size_t)koff * Cin * Cout;
#pragma unroll
    for (int r = 0; r < 32; r += 8) {
        float v = tile[tx][ty + r];
        __nv_bfloat16 h = __float2bfloat16(v);
        Thk[(size_t)(n0 + ty + r) * Cin + c0 + tx] = h;
        Tlk[(size_t)(n0 + ty + r) * Cin + c0 + tx] =
            __float2bfloat16(v - __bfloat162float(h));
    }
}

// ---------------- mma.sync conv-GEMM ----------------
// Y[m,n] = act( sum_{koff,c} X[m+koff-1,c] * WT[koff][n][c] + bias[n] )
// hi/lo bf16 split; per k16: D += Ah*Bh + Ah*Bl + Al*Bh.
// ACT: 0 none, 1 swish, 2 s6 epilogue. OUTF: 0 split bf16, 1 fp32.
#define ASTR 144                 // bytes per smem row (72 bf16), conflict-free ldsm
#define TILB (128 * ASTR)        // 18432 B per tile
#define STAGEB (4 * TILB)        // Ah, Al, Bh, Bl
#define GEMM_SMEM (2 * STAGEB)   // 147456 B

template <int ACT, int OUTF>
__global__ __launch_bounds__(256, 1) void mm_gemm(
    const __nv_bfloat16* __restrict__ Ah, const __nv_bfloat16* __restrict__ Al,
    const __nv_bfloat16* __restrict__ Wh, const __nv_bfloat16* __restrict__ Wl,
    const float* __restrict__ bias, int Cin, int Cout,
    __nv_bfloat16* __restrict__ Yh, __nv_bfloat16* __restrict__ Yl,
    float* __restrict__ Yf,
    const __nv_bfloat16* __restrict__ xch, const __nv_bfloat16* __restrict__ xcl,
    const __nv_bfloat16* __restrict__ xrh, const __nv_bfloat16* __restrict__ xrl,
    const float* __restrict__ cbv) {
    extern __shared__ char smem[];
    const uint32_t sb = s2u(smem);
    const int tid = threadIdx.x;
    const int wid = tid >> 5;
    const int lane = tid & 31;
    const int warp_m = wid >> 2;        // 0..1
    const int warp_n = wid & 3;         // 0..3
    const int bm = blockIdx.y * 128;
    const int bn = blockIdx.x * 128;

    const int KC = Cin >> 6;            // 64-wide k-chunks per tap
    const int nch = 3 * KC;

    // loader mapping: row = tid/2, 4x16B segs starting at (tid&1)*64B
    const int lr = tid >> 1;
    const int lseg = (tid & 1) * 4;
    const int pos = (bm + lr) & LMASK;

    float acc[4][4][4];
#pragma unroll
    for (int i = 0; i < 4; i++)
#pragma unroll
        for (int j = 0; j < 4; j++)
#pragma unroll
            for (int q = 0; q < 4; q++) acc[i][j][q] = 0.f;

    auto issue_loads = [&](int cc) {
        int s = cc & 1;
        int koff = cc / KC;
        int kc = (cc - koff * KC) << 6;
        uint32_t st = sb + s * STAGEB + lr * ASTR + lseg * 16;
        // A tiles
        bool av = !((koff == 0 && pos == 0) || (koff == 2 && pos == LMASK));
        uint32_t asz = av ? 16u : 0u;
        long long arow = (long long)(bm + lr) + koff - 1;
        const __nv_bfloat16* pa = Ah + arow * Cin + kc + lseg * 8;
        const __nv_bfloat16* pl = Al + arow * Cin + kc + lseg * 8;
#pragma unroll
        for (int i = 0; i < 4; i++) {
            cp16(st + 0 * TILB + i * 16, pa + i * 8, asz);
            cp16(st + 1 * TILB + i * 16, pl + i * 8, asz);
        }
        // B tiles
        size_t boff = ((size_t)koff * Cout + bn + lr) * Cin + kc + lseg * 8;
        const __nv_bfloat16* pbh = Wh + boff;
        const __nv_bfloat16* pbl = Wl + boff;
#pragma unroll
        for (int i = 0; i < 4; i++) {
            cp16(st + 2 * TILB + i * 16, pbh + i * 8, 16u);
            cp16(st + 3 * TILB + i * 16, pbl + i * 8, 16u);
        }
    };

    issue_loads(0);
    cp_commit();

    // ldmatrix address components (row part varies by k16 only via column)
    const int a_row = warp_m * 64 + (lane & 15);
    const int a_kh = (lane >> 4) * 8;               // bf16 elems
    const int mi = lane >> 3;                       // 0..3
    const int b_rowbase = warp_n * 32 + ((mi >> 1) << 3) + (lane & 7);
    const int b_kh = (mi & 1) * 8;

    for (int cc = 0; cc < nch; cc++) {
        if (cc + 1 < nch) {
            issue_loads(cc + 1);
            cp_commit();
            cp_wait<1>();
        } else {
            cp_wait<0>();
        }
        __syncthreads();

        uint32_t stage = sb + (cc & 1) * STAGEB;
#pragma unroll
        for (int k16 = 0; k16 < 4; k16++) {
            uint32_t ah[4][4], al[4][4];
#pragma unroll
            for (int mt = 0; mt < 4; mt++) {
                uint32_t addr = stage + (a_row + mt * 16) * ASTR +
                                (k16 * 16 + a_kh) * 2;
                ldsm4(ah[mt], addr);
                ldsm4(al[mt], addr + TILB);
            }
            uint32_t bh[4][2], bl[4][2];
#pragma unroll
            for (int p = 0; p < 2; p++) {
                uint32_t addr = stage + 2 * TILB + (b_rowbase + p * 16) * ASTR +
                                (k16 * 16 + b_kh) * 2;
                uint32_t t4[4];
                ldsm4(t4, addr);
                bh[2 * p][0] = t4[0]; bh[2 * p][1] = t4[1];
                bh[2 * p + 1][0] = t4[2]; bh[2 * p + 1][1] = t4[3];
                ldsm4(t4, addr + TILB);
                bl[2 * p][0] = t4[0]; bl[2 * p][1] = t4[1];
                bl[2 * p + 1][0] = t4[2]; bl[2 * p + 1][1] = t4[3];
            }
#pragma unroll
            for (int mt = 0; mt < 4; mt++) {
#pragma unroll
                for (int nt = 0; nt < 4; nt++) {
                    mma16816(acc[mt][nt], ah[mt], bh[nt]);
                    mma16816(acc[mt][nt], ah[mt], bl[nt]);
                    mma16816(acc[mt][nt], al[mt], bh[nt]);
                }
            }
        }
        __syncthreads();
    }

    // ---------------- epilogue ----------------
    const int m0 = bm + warp_m * 64 + (lane >> 2);
    const int n0 = bn + warp_n * 32 + (lane & 3) * 2;
#pragma unroll
    for (int mt = 0; mt < 4; mt++) {
        int r0 = m0 + mt * 16;
        float cb0 = 0.f, cb1 = 0.f;
        if (ACT == 2) { cb0 = cbv[r0]; cb1 = cbv[r0 + 8]; }
#pragma unroll
        for (int h = 0; h < 2; h++) {
            int row = r0 + h * 8;
            float cbs = h ? cb1 : cb0;
            size_t ybase = (size_t)row * Cout;
#pragma unroll
            for (int nt = 0; nt < 4; nt++) {
                int col = n0 + nt * 8;
                float v0 = acc[mt][nt][2 * h + 0] + bias[col];
                float v1 = acc[mt][nt][2 * h + 1] + bias[col + 1];
                if (ACT == 1) { v0 = swish_f(v0); v1 = swish_f(v1); }
                if (ACT == 2) {
                    size_t o = ybase + col;
                    __nv_bfloat162 ch = *(const __nv_bfloat162*)(xch + o);
                    __nv_bfloat162 cl = *(const __nv_bfloat162*)(xcl + o);
                    __nv_bfloat162 rh = *(const __nv_bfloat162*)(xrh + o);
                    __nv_bfloat162 rl = *(const __nv_bfloat162*)(xrl + o);
                    float xc0 = __bfloat162float(ch.x) + __bfloat162float(cl.x);
                    float xc1 = __bfloat162float(ch.y) + __bfloat162float(cl.y);
                    float xr0 = __bfloat162float(rh.x) + __bfloat162float(rl.x);
                    float xr1 = __bfloat162float(rh.y) + __bfloat162float(rl.y);
                    v0 = xc0 * softplus_f(v0) * cbs * xr0;
                    v1 = xc1 * softplus_f(v1) * cbs * xr1;
                }
                if (OUTF == 0) {
                    __nv_bfloat16 h0 = __float2bfloat16(v0);
                    __nv_bfloat16 h1 = __float2bfloat16(v1);
                    __nv_bfloat162 hp; hp.x = h0; hp.y = h1;
                    *(__nv_bfloat162*)(Yh + ybase + col) = hp;
                    __nv_bfloat162 lp;
                    lp.x = __float2bfloat16(v0 - __bfloat162float(h0));
                    lp.y = __float2bfloat16(v1 - __bfloat162float(h1));
                    *(__nv_bfloat162*)(Yl + ybase + col) = lp;
                } else {
                    *(float2*)(Yf + ybase + col) = make_float2(v0, v1);
                }
            }
        }
    }
}

// ---------------- fused fc2/fc3 conv + cb scalar (reads hi/lo) ----------------
__global__ void bc_kernel(const __nv_bfloat16* __restrict__ Xh,
                          const __nv_bfloat16* __restrict__ Xl,
                          const float* __restrict__ w2, const float* __restrict__ b2,
                          const float* __restrict__ w3, const float* __restrict__ b3,
                          float* __restrict__ cbout, int M) {
    int warp = (int)((blockIdx.x * blockDim.x + threadIdx.x) >> 5);
    int lane = threadIdx.x & 31;
    if (warp >= M) return;
    float accB[NS], accC[NS];
#pragma unroll
    for (int n = 0; n < NS; n++) { accB[n] = 0.f; accC[n] = 0.f; }
    int pos = warp & LMASK;
    for (int koff = 0; koff < 3; koff++) {
        if ((koff == 0 && pos == 0) || (koff == 2 && pos == LMASK)) continue;
        const __nv_bfloat16* xh = Xh + (size_t)(warp + koff - 1) * D2;
        const __nv_bfloat16* xl = Xl + (size_t)(warp + koff - 1) * D2;
        const float* w2k = w2 + (size_t)koff * D2 * NS;
        const float* w3k = w3 + (size_t)koff * D2 * NS;
        for (int c = lane; c < D2; c += 32) {
            float xv = __bfloat162float(xh[c]) + __bfloat162float(xl[c]);
            const float4* w2p = (const float4*)(w2k + (size_t)c * NS);
            const float4* w3p = (const float4*)(w3k + (size_t)c * NS);
#pragma unroll
            for (int q = 0; q < 4; q++) {
                float4 wv = w2p[q];
                accB[q * 4 + 0] += xv * wv.x;
                accB[q * 4 + 1] += xv * wv.y;
                accB[q * 4 + 2] += xv * wv.z;
                accB[q * 4 + 3] += xv * wv.w;
                float4 wv3 = w3p[q];
                accC[q * 4 + 0] += xv * wv3.x;
                accC[q * 4 + 1] += xv * wv3.y;
                accC[q * 4 + 2] += xv * wv3.z;
                accC[q * 4 + 3] += xv * wv3.w;
            }
        }
    }
#pragma unroll
    for (int n = 0; n < NS; n++) {
#pragma unroll
        for (int off = 16; off; off >>= 1) {
            accB[n] += __shfl_xor_sync(0xffffffffu, accB[n], off);
            accC[n] += __shfl_xor_sync(0xffffffffu, accC[n], off);
        }
    }
    if (lane == 0) {
        float s = 0.f;
#pragma unroll
        for (int n = 0; n < NS; n++) s += (accB[n] + b2[n]) * (accC[n] + b3[n]);
        cbout[warp] = s;
    }
}

// ---------------- launch ----------------
extern "C" void kernel_launch(void* const* d_in, const int* in_sizes, int n_in,
                              void* d_out, int out_size) {
    const float* x      = (const float*)d_in[0];
    const float* norm_w = (const float*)d_in[1];
    const float* inp_w  = (const float*)d_in[2];
    const float* inp_b  = (const float*)d_in[3];
    const float* conv_w = (const float*)d_in[4];
    const float* conv_b = (const float*)d_in[5];
    const float* cl_w   = (const float*)d_in[6];
    const float* cl_b   = (const float*)d_in[7];
    const float* fc1_w  = (const float*)d_in[8];
    const float* fc1_b  = (const float*)d_in[9];
    const float* fc2_w  = (const float*)d_in[10];
    const float* fc2_b  = (const float*)d_in[11];
    const float* fc3_w  = (const float*)d_in[12];
    const float* fc3_b  = (const float*)d_in[13];
    // d_in[14] = A (mathematically dead)
    const float* res_w  = (const float*)d_in[15];
    const float* res_b  = (const float*)d_in[16];
    const float* out_w  = (const float*)d_in[17];
    const float* out_b  = (const float*)d_in[18];

    int M = in_sizes[0] / D1;  // 16384

    __nv_bfloat16 *xnh, *xnl, *t0h, *t0l, *t1h, *t1l, *t2h, *t2l;
    __nv_bfloat16 *wInpH, *wInpL, *wCnvH, *wCnvL, *wClH, *wClL;
    __nv_bfloat16 *wF1H, *wF1L, *wResH, *wResL, *wOutH, *wOutL;
    float* cb;
    cudaGetSymbolAddress((void**)&xnh, g_xnh);
    cudaGetSymbolAddress((void**)&xnl, g_xnl);
    cudaGetSymbolAddress((void**)&t0h, g_t0h);
    cudaGetSymbolAddress((void**)&t0l, g_t0l);
    cudaGetSymbolAddress((void**)&t1h, g_t1h);
    cudaGetSymbolAddress((void**)&t1l, g_t1l);
    cudaGetSymbolAddress((void**)&t2h, g_t2h);
    cudaGetSymbolAddress((void**)&t2l, g_t2l);
    cudaGetSymbolAddress((void**)&cb, g_cb);
    cudaGetSymbolAddress((void**)&wInpH, g_wInpH);
    cudaGetSymbolAddress((void**)&wInpL, g_wInpL);
    cudaGetSymbolAddress((void**)&wCnvH, g_wCnvH);
    cudaGetSymbolAddress((void**)&wCnvL, g_wCnvL);
    cudaGetSymbolAddress((void**)&wClH, g_wClH);
    cudaGetSymbolAddress((void**)&wClL, g_wClL);
    cudaGetSymbolAddress((void**)&wF1H, g_wF1H);
    cudaGetSymbolAddress((void**)&wF1L, g_wF1L);
    cudaGetSymbolAddress((void**)&wResH, g_wResH);
    cudaGetSymbolAddress((void**)&wResL, g_wResL);
    cudaGetSymbolAddress((void**)&wOutH, g_wOutH);
    cudaGetSymbolAddress((void**)&wOutL, g_wOutL);

    cudaFuncSetAttribute(mm_gemm<0, 0>, cudaFuncAttributeMaxDynamicSharedMemorySize, GEMM_SMEM);
    cudaFuncSetAttribute(mm_gemm<1, 0>, cudaFuncAttributeMaxDynamicSharedMemorySize, GEMM_SMEM);
    cudaFuncSetAttribute(mm_gemm<2, 0>, cudaFuncAttributeMaxDynamicSharedMemorySize, GEMM_SMEM);
    cudaFuncSetAttribute(mm_gemm<0, 1>, cudaFuncAttributeMaxDynamicSharedMemorySize, GEMM_SMEM);

    // weight transpose+split
    dim3 wblk(32, 8);
    wsplit_T<<<dim3(D2 / 32, D1 / 32, 3), wblk>>>(inp_w, wInpH, wInpL, D1, D2);
    wsplit_T<<<dim3(D2 / 32, D2 / 32, 3), wblk>>>(conv_w, wCnvH, wCnvL, D2, D2);
    wsplit_T<<<dim3(D2 / 32, D2 / 32, 3), wblk>>>(cl_w, wClH, wClL, D2, D2);
    wsplit_T<<<dim3(D2 / 32, D2 / 32, 3), wblk>>>(fc1_w, wF1H, wF1L, D2, D2);
    wsplit_T<<<dim3(D2 / 32, D1 / 32, 3), wblk>>>(res_w, wResH, wResL, D1, D2);
    wsplit_T<<<dim3(D1 / 32, D2 / 32, 3), wblk>>>(out_w, wOutH, wOutL, D2, D1);

    // 1) xn = rmsnorm(x) -> hi/lo
    rmsnorm_split<<<M, 128>>>(x, norm_w, xnh, xnl);

    dim3 blk(256);
    dim3 g_big(D2 / 128, M / 128);
    dim3 g_out(D1 / 128, M / 128);

    // 2) t0 = conv(xn, inp)
    mm_gemm<0, 0><<<g_big, blk, GEMM_SMEM>>>(xnh, xnl, wInpH, wInpL, inp_b, D1, D2,
        t0h, t0l, nullptr, nullptr, nullptr, nullptr, nullptr, nullptr);
    // 3) t1 = swish(conv(t0, conv))
    mm_gemm<1, 0><<<g_big, blk, GEMM_SMEM>>>(t0h, t0l, wCnvH, wCnvL, conv_b, D2, D2,
        t1h, t1l, nullptr, nullptr, nullptr, nullptr, nullptr, nullptr);
    // 4) t2 = conv(t1, cl) = x_conv_out
    mm_gemm<0, 0><<<g_big, blk, GEMM_SMEM>>>(t1h, t1l, wClH, wClL, cl_b, D2, D2,
        t2h, t2l, nullptr, nullptr, nullptr, nullptr, nullptr, nullptr);
    // 5) cb[m]
    bc_kernel<<<(M * 32 + 255) / 256, 256>>>(t2h, t2l, fc2_w, fc2_b, fc3_w, fc3_b, cb, M);
    // 6) t1 = x_res = swish(conv(xn, res))
    mm_gemm<1, 0><<<g_big, blk, GEMM_SMEM>>>(xnh, xnl, wResH, wResL, res_b, D1, D2,
        t1h, t1l, nullptr, nullptr, nullptr, nullptr, nullptr, nullptr);
    // 7) t0 = x_ssm * x_res (s6 epilogue)
    mm_gemm<2, 0><<<g_big, blk, GEMM_SMEM>>>(t2h, t2l, wF1H, wF1L, fc1_b, D2, D2,
        t0h, t0l, nullptr, t2h, t2l, t1h, t1l, cb);
    // 8) out = conv(t0, out) -> fp32
    mm_gemm<0, 1><<<g_out, blk, GEMM_SMEM>>>(t0h, t0l, wOutH, wOutL, out_b, D2, D1,
        nullptr, nullptr, (float*)d_out, nullptr, nullptr, nullptr, nullptr, nullptr);
}